// round 1
// baseline (speedup 1.0000x reference)
#include <cuda_runtime.h>
#include <math.h>

#define VOCAB   128000
#define TOPK    50
#define TOPP    0.9f
#define NEGV    (-1000000000.0f)
#define NBINS   4096
#define NCHUNK  (NBINS / 32)
#define CAP     4096
#define NT      1024

__device__ __forceinline__ unsigned int fkey(float f) {
    unsigned int u = __float_as_uint(f);
    // monotonic key: ascending key order == ascending float order
    return (u & 0x80000000u) ? ~u : (u | 0x80000000u);
}

__global__ __launch_bounds__(NT, 2)
void topk_topp_kernel(const float* __restrict__ logits, float* __restrict__ out) {
    __shared__ unsigned int hist[NBINS];
    __shared__ float buf[CAP];
    __shared__ unsigned int chunkSum[NCHUNK];
    __shared__ unsigned int s_cnt;
    __shared__ unsigned int s_thresh;    // threshold on (key >> 8); candidate iff (key>>8) >= s_thresh
    __shared__ unsigned int s_cntAbove;
    __shared__ int s_needRefine;
    __shared__ float s_vcut;
    __shared__ int s_ties;
    __shared__ unsigned int s_tiecnt;

    const int row = blockIdx.x;
    const float4* rp4 = (const float4*)(logits + (size_t)row * VOCAB);
    float4* op4 = (float4*)(out + (size_t)row * VOCAB);
    const int tid = threadIdx.x;
    const int nvec = VOCAB / 4;

    // ---------------- pass 1: histogram of top 12 key bits ----------------
    for (int i = tid; i < NBINS; i += NT) hist[i] = 0u;
    __syncthreads();
    for (int i = tid; i < nvec; i += NT) {
        float4 v = rp4[i];
        atomicAdd(&hist[fkey(v.x) >> 20], 1u);
        atomicAdd(&hist[fkey(v.y) >> 20], 1u);
        atomicAdd(&hist[fkey(v.z) >> 20], 1u);
        atomicAdd(&hist[fkey(v.w) >> 20], 1u);
    }
    __syncthreads();
    if (tid < NCHUNK) {
        unsigned int s = 0;
        #pragma unroll 8
        for (int j = 0; j < 32; j++) s += hist[tid * 32 + j];
        chunkSum[tid] = s;
    }
    __syncthreads();
    if (tid == 0) {
        unsigned int cum = 0;
        int b = 0;
        for (int c = NCHUNK - 1; c >= 0; c--) {
            if (cum + chunkSum[c] >= (unsigned)TOPK) {
                for (int j = 31; j >= 0; j--) {
                    int bin = c * 32 + j;
                    cum += hist[bin];
                    if (cum >= (unsigned)TOPK) { b = bin; break; }
                }
                break;
            }
            cum += chunkSum[c];
        }
        s_cntAbove = cum - hist[b];
        s_needRefine = (cum > (unsigned)CAP) ? 1 : 0;
        s_thresh = ((unsigned int)b) << 12;
        s_cnt = 0u;
    }
    __syncthreads();

    // ---------------- optional refinement (pathological bins only) ----------------
    if (s_needRefine) {
        unsigned int b = s_thresh >> 12;
        unsigned int above = s_cntAbove;
        for (int i = tid; i < NBINS; i += NT) hist[i] = 0u;
        __syncthreads();
        for (int i = tid; i < nvec; i += NT) {
            float4 v = rp4[i];
            unsigned int k0 = fkey(v.x), k1 = fkey(v.y), k2 = fkey(v.z), k3 = fkey(v.w);
            if ((k0 >> 20) == b) atomicAdd(&hist[(k0 >> 8) & 0xFFFu], 1u);
            if ((k1 >> 20) == b) atomicAdd(&hist[(k1 >> 8) & 0xFFFu], 1u);
            if ((k2 >> 20) == b) atomicAdd(&hist[(k2 >> 8) & 0xFFFu], 1u);
            if ((k3 >> 20) == b) atomicAdd(&hist[(k3 >> 8) & 0xFFFu], 1u);
        }
        __syncthreads();
        if (tid < NCHUNK) {
            unsigned int s = 0;
            #pragma unroll 8
            for (int j = 0; j < 32; j++) s += hist[tid * 32 + j];
            chunkSum[tid] = s;
        }
        __syncthreads();
        if (tid == 0) {
            unsigned int cum = above;
            int b2 = 0;
            for (int c = NCHUNK - 1; c >= 0; c--) {
                if (cum + chunkSum[c] >= (unsigned)TOPK) {
                    for (int j = 31; j >= 0; j--) {
                        int bin = c * 32 + j;
                        cum += hist[bin];
                        if (cum >= (unsigned)TOPK) { b2 = bin; break; }
                    }
                    break;
                }
                cum += chunkSum[c];
            }
            s_thresh = (b << 12) | (unsigned int)b2;
            s_cnt = 0u;
        }
        __syncthreads();
    }

    // ---------------- pass 2: collect candidates ----------------
    {
        unsigned int thr = s_thresh;
        for (int i = tid; i < nvec; i += NT) {
            float4 v = rp4[i];
            float vals[4] = {v.x, v.y, v.z, v.w};
            #pragma unroll
            for (int c = 0; c < 4; c++) {
                if ((fkey(vals[c]) >> 8) >= thr) {
                    unsigned int pos = atomicAdd(&s_cnt, 1u);
                    if (pos < (unsigned)CAP) buf[pos] = vals[c];
                }
            }
        }
    }
    __syncthreads();

    int C = (int)s_cnt; if (C > CAP) C = CAP;
    int N2 = 64; while (N2 < C) N2 <<= 1;
    for (int i = C + tid; i < N2; i += NT) buf[i] = __int_as_float(0xff800000); // -inf pad
    __syncthreads();

    // bitonic sort descending on buf[0..N2)
    for (unsigned int k = 2; k <= (unsigned)N2; k <<= 1) {
        for (unsigned int j = k >> 1; j > 0; j >>= 1) {
            for (unsigned int i = tid; i < (unsigned)N2; i += NT) {
                unsigned int ixj = i ^ j;
                if (ixj > i) {
                    float a = buf[i], c = buf[ixj];
                    bool up = ((i & k) == 0u);   // descending blocks
                    if (up ? (a < c) : (a > c)) { buf[i] = c; buf[ixj] = a; }
                }
            }
            __syncthreads();
        }
    }

    // ---------------- tiny top-p on sorted top-50 ----------------
    if (tid == 0) {
        int kk = (C < TOPK) ? C : TOPK;
        float vmax = buf[0];
        float e[TOPK];
        float s = 0.0f;
        for (int i = 0; i < kk; i++) { e[i] = expf(buf[i] - vmax); s += e[i]; }
        float cum = 0.0f;
        int m = kk;
        for (int i = 0; i < kk; i++) {
            cum += e[i] / s;                 // matches softmax-then-cumsum semantics
            if (cum > TOPP) { m = i + 1; break; }
        }
        float vcut = buf[m - 1];
        int g = 0;
        while (g < m && buf[g] > vcut) g++;
        s_vcut = vcut;
        s_ties = m - g;
        s_tiecnt = 0u;
    }
    __syncthreads();

    // ---------------- pass 3: write output ----------------
    {
        const float vcut = s_vcut;
        const unsigned int ties = (unsigned int)s_ties;
        for (int i = tid; i < nvec; i += NT) {
            float4 v = rp4[i];
            float4 o;
            o.x = (v.x > vcut) ? v.x : ((v.x == vcut) ? ((atomicAdd(&s_tiecnt, 1u) < ties) ? v.x : NEGV) : NEGV);
            o.y = (v.y > vcut) ? v.y : ((v.y == vcut) ? ((atomicAdd(&s_tiecnt, 1u) < ties) ? v.y : NEGV) : NEGV);
            o.z = (v.z > vcut) ? v.z : ((v.z == vcut) ? ((atomicAdd(&s_tiecnt, 1u) < ties) ? v.z : NEGV) : NEGV);
            o.w = (v.w > vcut) ? v.w : ((v.w == vcut) ? ((atomicAdd(&s_tiecnt, 1u) < ties) ? v.w : NEGV) : NEGV);
            op4[i] = o;
        }
    }
}

extern "C" void kernel_launch(void* const* d_in, const int* in_sizes, int n_in,
                              void* d_out, int out_size) {
    const float* logits = (const float*)d_in[0];
    float* out = (float*)d_out;
    int rows = in_sizes[0] / VOCAB;          // 32*8 = 256
    topk_topp_kernel<<<rows, NT>>>(logits, out);
}